// round 15
// baseline (speedup 1.0000x reference)
#include <cuda_runtime.h>

// FM forward: 2048 rows, 2 numeric + 4 categorical features, EMB=16, x int32.
// 4 lanes per row; each lane owns 4 embedding dims via one float4 per feature.
// Grid exactly covers 2048*4 = 8192 threads -> no bounds guard.
// Grid shape 32x256 is the best-measured config across the full sweep
// (ncu 4.32us best / harness 6.27us best). Identical-source runs: ncu
// 4.48/5.70/4.90/4.74/4.32/4.61us (stable at the single-launch latency
// floor); harness 6.27/6.91/6.50/23.97/16.03/6.62us (two infra-throttled
// outliers). Remaining harness deltas are environmental noise, not levers.
// v row layout: rows [0,1] numeric, then categorical blocks at offsets
//   user : base 2 + 0       (100000 rows)
//   item : base 2 + 100000  (50000 rows)
//   genre: base 2 + 150000  (20 rows)
//   year : base 2 + 150020  (100 rows)

__device__ __forceinline__ float4 ld4(const float* __restrict__ p) {
    return *reinterpret_cast<const float4*>(p);
}

__global__ __launch_bounds__(256, 1)
void FM_44538810859522_kernel(const int* __restrict__ x,
                              const float* __restrict__ v,
                              const float* __restrict__ bias_user,
                              const float* __restrict__ bias_item,
                              const float* __restrict__ bias_genre,
                              const float* __restrict__ bias_year,
                              float* __restrict__ out) {
    int t = blockIdx.x * blockDim.x + threadIdx.x;
    int b = t >> 2;        // row (0..2047)
    int j = t & 3;         // lane within row: owns dims [4j, 4j+4)

    // x row: 6 ints = 24B, 8B-aligned for all b -> three int2 loads.
    const int2* xr2 = reinterpret_cast<const int2*>(x + b * 6);
    int2 p0 = xr2[0];   // n0 n1
    int2 p1 = xr2[1];   // c0 c1
    int2 p2 = xr2[2];   // c2 c3

    int c0 = p1.x, c1 = p1.y, c2 = p2.x, c3 = p2.y;

    // Per-lane column offset into the 16-float embedding row (16B-aligned).
    int kc = j << 2;

    // 6 independent float4 gathers FIRST (MLP=6) — nothing ahead of them
    // but the x-load they depend on.
    float4 e0 = ld4(v + 0 * 16 + kc);
    float4 e1 = ld4(v + 1 * 16 + kc);
    float4 g0 = ld4(v + (2 +      0 + c0) * 16 + kc);
    float4 g1 = ld4(v + (2 + 100000 + c1) * 16 + kc);
    float4 g2 = ld4(v + (2 + 150000 + c2) * 16 + kc);
    float4 g3 = ld4(v + (2 + 150020 + c3) * 16 + kc);

    // Per-lane bias gather (lane j loads bias_j[c_j]); select chain sits
    // behind the gather issue, and the load overlaps the gather latency.
    const float* bp = (j == 0) ? bias_user
                    : (j == 1) ? bias_item
                    : (j == 2) ? bias_genre
                               : bias_year;
    int bi = (j == 0) ? c0 : (j == 1) ? c1 : (j == 2) ? c2 : c3;
    float bias = bp[bi];

    float n0 = (float)p0.x;
    float n1 = (float)p0.y;

    float r = bias;
    #pragma unroll
    for (int q = 0; q < 4; q++) {
        float a0 = n0 * ((&e0.x)[q]);
        float a1 = n1 * ((&e1.x)[q]);
        float w0 = (&g0.x)[q], w1 = (&g1.x)[q], w2 = (&g2.x)[q], w3 = (&g3.x)[q];
        float s  = a0 + a1 + w0 + w1 + w2 + w3;
        float ss = a0*a0 + a1*a1 + w0*w0 + w1*w1 + w2*w2 + w3*w3;
        r += 0.5f * (s * s - ss);
    }

    // Reduce over the 4 lanes of this row (2 shfl rounds).
    r += __shfl_xor_sync(0xFFFFFFFFu, r, 1);
    r += __shfl_xor_sync(0xFFFFFFFFu, r, 2);

    if (j == 0)
        out[b] = 1.0f / (1.0f + __expf(-r));
}

extern "C" void kernel_launch(void* const* d_in, const int* in_sizes, int n_in,
                              void* d_out, int out_size) {
    const int*   x          = (const int*)d_in[0];
    const float* v          = (const float*)d_in[1];
    const float* bias_user  = (const float*)d_in[2];
    const float* bias_item  = (const float*)d_in[3];
    const float* bias_genre = (const float*)d_in[4];
    const float* bias_year  = (const float*)d_in[5];
    float* out = (float*)d_out;

    // 2048 rows * 4 lanes = 8192 threads -> 32 blocks of 256
    // (best-measured configuration of the CTA-count sweep).
    FM_44538810859522_kernel<<<32, 256>>>(x, v, bias_user, bias_item,
                                          bias_genre, bias_year, out);
}

// round 16
// speedup vs baseline: 1.0670x; 1.0670x over previous
#include <cuda_runtime.h>

// FM forward: 2048 rows, 2 numeric + 4 categorical features, EMB=16, x int32.
// 4 lanes per row; each lane owns 4 embedding dims via one float4 per feature.
// Grid exactly covers 2048*4 = 8192 threads -> no bounds guard.
// Grid shape 32x256 is the best-measured config across the full sweep
// (ncu 4.32us best / harness 6.27us best). Identical-source runs: ncu
// 4.48/5.70/4.90/4.74/4.32/4.61/4.54us (stable at the single-launch
// latency floor); harness 6.27/6.91/6.50/23.97/16.03/6.62/6.62us (two
// infra-throttled outliers). ~4.2us of the kernel time is fixed
// launch/ramp cost invariant to grid shape and body structure; every
// remaining candidate lever is 10-30x below the +-0.5us noise floor.
// v row layout: rows [0,1] numeric, then categorical blocks at offsets
//   user : base 2 + 0       (100000 rows)
//   item : base 2 + 100000  (50000 rows)
//   genre: base 2 + 150000  (20 rows)
//   year : base 2 + 150020  (100 rows)

__device__ __forceinline__ float4 ld4(const float* __restrict__ p) {
    return *reinterpret_cast<const float4*>(p);
}

__global__ __launch_bounds__(256, 1)
void FM_44538810859522_kernel(const int* __restrict__ x,
                              const float* __restrict__ v,
                              const float* __restrict__ bias_user,
                              const float* __restrict__ bias_item,
                              const float* __restrict__ bias_genre,
                              const float* __restrict__ bias_year,
                              float* __restrict__ out) {
    int t = blockIdx.x * blockDim.x + threadIdx.x;
    int b = t >> 2;        // row (0..2047)
    int j = t & 3;         // lane within row: owns dims [4j, 4j+4)

    // x row: 6 ints = 24B, 8B-aligned for all b -> three int2 loads.
    const int2* xr2 = reinterpret_cast<const int2*>(x + b * 6);
    int2 p0 = xr2[0];   // n0 n1
    int2 p1 = xr2[1];   // c0 c1
    int2 p2 = xr2[2];   // c2 c3

    int c0 = p1.x, c1 = p1.y, c2 = p2.x, c3 = p2.y;

    // Per-lane column offset into the 16-float embedding row (16B-aligned).
    int kc = j << 2;

    // 6 independent float4 gathers FIRST (MLP=6) — nothing ahead of them
    // but the x-load they depend on.
    float4 e0 = ld4(v + 0 * 16 + kc);
    float4 e1 = ld4(v + 1 * 16 + kc);
    float4 g0 = ld4(v + (2 +      0 + c0) * 16 + kc);
    float4 g1 = ld4(v + (2 + 100000 + c1) * 16 + kc);
    float4 g2 = ld4(v + (2 + 150000 + c2) * 16 + kc);
    float4 g3 = ld4(v + (2 + 150020 + c3) * 16 + kc);

    // Per-lane bias gather (lane j loads bias_j[c_j]); select chain sits
    // behind the gather issue, and the load overlaps the gather latency.
    const float* bp = (j == 0) ? bias_user
                    : (j == 1) ? bias_item
                    : (j == 2) ? bias_genre
                               : bias_year;
    int bi = (j == 0) ? c0 : (j == 1) ? c1 : (j == 2) ? c2 : c3;
    float bias = bp[bi];

    float n0 = (float)p0.x;
    float n1 = (float)p0.y;

    float r = bias;
    #pragma unroll
    for (int q = 0; q < 4; q++) {
        float a0 = n0 * ((&e0.x)[q]);
        float a1 = n1 * ((&e1.x)[q]);
        float w0 = (&g0.x)[q], w1 = (&g1.x)[q], w2 = (&g2.x)[q], w3 = (&g3.x)[q];
        float s  = a0 + a1 + w0 + w1 + w2 + w3;
        float ss = a0*a0 + a1*a1 + w0*w0 + w1*w1 + w2*w2 + w3*w3;
        r += 0.5f * (s * s - ss);
    }

    // Reduce over the 4 lanes of this row (2 shfl rounds).
    r += __shfl_xor_sync(0xFFFFFFFFu, r, 1);
    r += __shfl_xor_sync(0xFFFFFFFFu, r, 2);

    if (j == 0)
        out[b] = 1.0f / (1.0f + __expf(-r));
}

extern "C" void kernel_launch(void* const* d_in, const int* in_sizes, int n_in,
                              void* d_out, int out_size) {
    const int*   x          = (const int*)d_in[0];
    const float* v          = (const float*)d_in[1];
    const float* bias_user  = (const float*)d_in[2];
    const float* bias_item  = (const float*)d_in[3];
    const float* bias_genre = (const float*)d_in[4];
    const float* bias_year  = (const float*)d_in[5];
    float* out = (float*)d_out;

    // 2048 rows * 4 lanes = 8192 threads -> 32 blocks of 256
    // (best-measured configuration of the CTA-count sweep).
    FM_44538810859522_kernel<<<32, 256>>>(x, v, bias_user, bias_item,
                                          bias_genre, bias_year, out);
}